// round 14
// baseline (speedup 1.0000x reference)
#include <cuda_runtime.h>
#include <cuda_fp16.h>

#define NN 100000
#define EE 800000
#define FULL 0xffffffffu

typedef unsigned long long u64t;

// ---- f32x2 packed-math helpers (Blackwell FFMA2 path, PTX-only) ----
__device__ __forceinline__ u64t pk2(float lo, float hi) {
    u64t r; asm("mov.b64 %0, {%1, %2};" : "=l"(r) : "f"(lo), "f"(hi)); return r;
}
__device__ __forceinline__ void up2(float& lo, float& hi, u64t v) {
    asm("mov.b64 {%0, %1}, %2;" : "=f"(lo), "=f"(hi) : "l"(v));
}
__device__ __forceinline__ u64t fma2_(u64t a, u64t b, u64t c) {
    u64t d; asm("fma.rn.f32x2 %0, %1, %2, %3;" : "=l"(d) : "l"(a), "l"(b), "l"(c)); return d;
}
__device__ __forceinline__ u64t mul2_(u64t a, u64t b) {
    u64t d; asm("mul.rn.f32x2 %0, %1, %2;" : "=l"(d) : "l"(a), "l"(b)); return d;
}
__device__ __forceinline__ u64t add2_(u64t a, u64t b) {
    u64t d; asm("add.rn.f32x2 %0, %1, %2;" : "=l"(d) : "l"(a), "l"(b)); return d;
}
__device__ __forceinline__ float c4(const float4 v, int k) {
    return k == 0 ? v.x : k == 1 ? v.y : k == 2 ? v.z : v.w;
}

// ---------------- device scratch (no allocs allowed) ----------------
__device__ __half g_kvh[NN * 256];   // [n][0:128)=key, [n][128:256)=value, fp16
__device__ __half g_qh[NN * 128];    // query, fp16
__device__ float  g_aggr[NN * 128];
__device__ float  g_G[NN * 64];
__device__ float  g_denom[NN * 4];
__device__ float  g_wrbf[42 * 32];
__device__ float  g_wsbf[16 * 32];

// ---------------- K0: fold weight pairs ----------------
__global__ void combine_weights_kernel(const float* __restrict__ w_rbf0,
                                       const float* __restrict__ w_rbf1,
                                       const float* __restrict__ w_sbf0,
                                       const float* __restrict__ w_sbf1)
{
    int t = blockIdx.x * blockDim.x + threadIdx.x;
    if (t < 42 * 32) {
        int i = t >> 5, o = t & 31;
        float s = 0.f;
        #pragma unroll
        for (int k = 0; k < 32; k++) s = fmaf(w_rbf0[i * 32 + k], w_rbf1[k * 32 + o], s);
        g_wrbf[t] = s;
    }
    if (t < 16 * 32) {
        int i = t >> 5, o = t & 31;
        float s = 0.f;
        #pragma unroll
        for (int k = 0; k < 32; k++) s = fmaf(w_sbf0[i * 32 + k], w_sbf1[k * 32 + o], s);
        g_wsbf[t] = s;
    }
}

// ---------------- dummy: aligns ncu -s 5 onto edge_kernel ----------------
__global__ void profile_align_kernel() {}

// ---------------- K1: per-node K/Q/V/skip + G, 4 nodes per warp iter ----------------
__global__ __launch_bounds__(256, 2)
void node_kernel(const float* __restrict__ x, const float* __restrict__ rbf,
                 const float* __restrict__ w_ek,
                 const float* __restrict__ w_k, const float* __restrict__ b_k,
                 const float* __restrict__ w_q, const float* __restrict__ b_q,
                 const float* __restrict__ w_v, const float* __restrict__ b_v,
                 const float* __restrict__ w_skip, const float* __restrict__ b_skip,
                 float* __restrict__ out)
{
    extern __shared__ float sm[];
    float* sw_k    = sm;
    float* sw_q    = sm + 4096;
    float* sw_v    = sm + 8192;
    float* sw_s    = sm + 12288;
    float* sw_ek   = sm + 16384;
    float* sw_rbfc = sm + 18432;
    float* sb      = sm + 19776;

    for (int i = threadIdx.x; i < 4096; i += blockDim.x) {
        sw_k[i] = w_k[i]; sw_q[i] = w_q[i]; sw_v[i] = w_v[i]; sw_s[i] = w_skip[i];
    }
    for (int i = threadIdx.x; i < 2048; i += blockDim.x) sw_ek[i] = w_ek[i];
    for (int i = threadIdx.x; i < 1344; i += blockDim.x) sw_rbfc[i] = g_wrbf[i];
    for (int i = threadIdx.x; i < 128; i += blockDim.x) {
        sb[i] = b_k[i]; sb[128 + i] = b_q[i]; sb[256 + i] = b_v[i]; sb[384 + i] = b_skip[i];
    }
    __syncthreads();

    int lane = threadIdx.x & 31;
    int r = lane & 7;
    int gw = (blockIdx.x * blockDim.x + threadIdx.x) >> 5;
    int nw = (gridDim.x * blockDim.x) >> 5;

    for (int n0 = gw * 4; n0 < NN; n0 += nw * 4) {
        float f[4] = {0.f, 0.f, 0.f, 0.f};
        const float* rn = rbf + (size_t)n0 * 42;
        #pragma unroll 6
        for (int i = 0; i < 42; i++) {
            float w = sw_rbfc[i * 32 + lane];
            f[0] = fmaf(__ldg(rn + i),       w, f[0]);
            f[1] = fmaf(__ldg(rn + 42 + i),  w, f[1]);
            f[2] = fmaf(__ldg(rn + 84 + i),  w, f[2]);
            f[3] = fmaf(__ldg(rn + 126 + i), w, f[3]);
        }
        float xv[4], xs[4];
        #pragma unroll
        for (int j = 0; j < 4; j++) {
            xv[j] = __ldg(x + (size_t)(n0 + j) * 32 + lane);
            xs[j] = f[j] * xv[j];
        }

        ulonglong2 bK = *(const ulonglong2*)(sb + 4 * lane);
        ulonglong2 bQ = *(const ulonglong2*)(sb + 128 + 4 * lane);
        ulonglong2 bV = *(const ulonglong2*)(sb + 256 + 4 * lane);
        ulonglong2 bS = *(const ulonglong2*)(sb + 384 + 4 * lane);
        u64t aK[4][2], aQ[4][2], aV[4][2], aS[4][2];
        #pragma unroll
        for (int j = 0; j < 4; j++) {
            aK[j][0] = bK.x; aK[j][1] = bK.y;
            aQ[j][0] = bQ.x; aQ[j][1] = bQ.y;
            aV[j][0] = bV.x; aV[j][1] = bV.y;
            aS[j][0] = bS.x; aS[j][1] = bS.y;
        }

        #pragma unroll 8
        for (int c = 0; c < 32; c++) {
            ulonglong2 wk = *(const ulonglong2*)(sw_k + c * 128 + 4 * lane);
            ulonglong2 wq = *(const ulonglong2*)(sw_q + c * 128 + 4 * lane);
            ulonglong2 wv = *(const ulonglong2*)(sw_v + c * 128 + 4 * lane);
            ulonglong2 ws = *(const ulonglong2*)(sw_s + c * 128 + 4 * lane);
            #pragma unroll
            for (int j = 0; j < 4; j++) {
                float ms = __shfl_sync(FULL, xs[j], c);
                float mx = __shfl_sync(FULL, xv[j], c);
                u64t pms = pk2(ms, ms);
                u64t pmx = pk2(mx, mx);
                aK[j][0] = fma2_(pms, wk.x, aK[j][0]); aK[j][1] = fma2_(pms, wk.y, aK[j][1]);
                aQ[j][0] = fma2_(pmx, wq.x, aQ[j][0]); aQ[j][1] = fma2_(pmx, wq.y, aQ[j][1]);
                aV[j][0] = fma2_(pms, wv.x, aV[j][0]); aV[j][1] = fma2_(pms, wv.y, aV[j][1]);
                aS[j][0] = fma2_(pmx, ws.x, aS[j][0]); aS[j][1] = fma2_(pmx, ws.y, aS[j][1]);
            }
        }

        #pragma unroll
        for (int j = 0; j < 4; j++) {
            float4 K, V, Q, S;
            up2(K.x, K.y, aK[j][0]); up2(K.z, K.w, aK[j][1]);
            up2(V.x, V.y, aV[j][0]); up2(V.z, V.w, aV[j][1]);
            up2(Q.x, Q.y, aQ[j][0]); up2(Q.z, Q.w, aQ[j][1]);
            up2(S.x, S.y, aS[j][0]); up2(S.z, S.w, aS[j][1]);
            uint2 st;
            *(half2*)&st.x = __floats2half2_rn(K.x, K.y);
            *(half2*)&st.y = __floats2half2_rn(K.z, K.w);
            *(uint2*)(g_kvh + (size_t)(n0 + j) * 256 + 4 * lane) = st;
            *(half2*)&st.x = __floats2half2_rn(V.x, V.y);
            *(half2*)&st.y = __floats2half2_rn(V.z, V.w);
            *(uint2*)(g_kvh + (size_t)(n0 + j) * 256 + 128 + 4 * lane) = st;
            *(half2*)&st.x = __floats2half2_rn(Q.x, Q.y);
            *(half2*)&st.y = __floats2half2_rn(Q.z, Q.w);
            *(uint2*)(g_qh + (size_t)(n0 + j) * 128 + 4 * lane) = st;
            ulonglong2 o;
            o.x = aS[j][0]; o.y = aS[j][1];
            *(ulonglong2*)(out + (size_t)(n0 + j) * 128 + 4 * lane) = o;
        }

        // G[n][h][i] = sum_{c in head h} w_ek[i][h*32+c] * query[h*32+c]  (f32 q)
        float4 q[4];
        #pragma unroll
        for (int j = 0; j < 4; j++) {
            up2(q[j].x, q[j].y, aQ[j][0]);
            up2(q[j].z, q[j].w, aQ[j][1]);
        }
        float G0[4] = {0.f,0.f,0.f,0.f}, G1[4] = {0.f,0.f,0.f,0.f};
        #pragma unroll
        for (int i = 0; i < 16; i++) {
            float4 we = *(const float4*)(sw_ek + i * 128 + 4 * lane);
            #pragma unroll
            for (int j = 0; j < 4; j++) {
                float p = we.x * q[j].x + we.y * q[j].y + we.z * q[j].z + we.w * q[j].w;
                p += __shfl_xor_sync(FULL, p, 1);
                p += __shfl_xor_sync(FULL, p, 2);
                p += __shfl_xor_sync(FULL, p, 4);
                if ((i >> 1) == r) { if (i & 1) G1[j] = p; else G0[j] = p; }
            }
        }
        #pragma unroll
        for (int j = 0; j < 4; j++)
            *(float2*)(g_G + (size_t)(n0 + j) * 64 + (lane >> 3) * 16 + 2 * r)
                = make_float2(G0[j], G1[j]);
    }
}

// ---------------- K2: edge pass, register-resident w_ev, fp16 gathers ----------------
__global__ __launch_bounds__(256, 2)
void edge_kernel(const float* __restrict__ edge_attr, const float* __restrict__ sbf,
                 const float* __restrict__ w_ev, const int* __restrict__ ei)
{
    __shared__ __align__(16) float sw_sf[512];
    for (int i = threadIdx.x; i < 512; i += blockDim.x) sw_sf[i] = g_wsbf[i];
    __syncthreads();

    int lane = threadIdx.x & 31;
    int r = lane & 7;
    int h = lane >> 3;
    int gw = (blockIdx.x * blockDim.x + threadIdx.x) >> 5;
    int nw = (gridDim.x * blockDim.x) >> 5;
    const float inv_sqrt_c = 0.17677669529663687f;

    // w_ev columns [4*lane, 4*lane+4) for all 16 rows -> 32 packed u64 regs
    u64t wl[16], wh[16];
    #pragma unroll
    for (int i = 0; i < 16; i++) {
        float4 w = __ldg((const float4*)(w_ev + i * 128 + 4 * lane));
        wl[i] = pk2(w.x, w.y);
        wh[i] = pk2(w.z, w.w);
    }

    for (int e = gw; e < EE; e += nw) {
        int src = __ldg(ei + e);
        int dst = __ldg(ei + EE + e);

        // edge_attr row: uniform loads (broadcast) + per-lane scalar for alpha
        const float4* eap = (const float4*)(edge_attr + (size_t)e * 16);
        float4 ea[4];
        #pragma unroll
        for (int i = 0; i < 4; i++) ea[i] = __ldg(eap + i);
        float eav = __ldg(edge_attr + (size_t)e * 16 + (lane & 15));

        // edge_val GEMV: weights in registers, multipliers warp-uniform
        u64t evl = 0, evh = 0;
        #pragma unroll
        for (int i = 0; i < 16; i++) {
            float a = c4(ea[i >> 2], i & 3);
            u64t pa = pk2(a, a);
            evl = fma2_(pa, wl[i], evl);
            evh = fma2_(pa, wh[i], evh);
        }

        // fp16 gathers: key+value in one 512B record, query 256B
        uint2 kr = __ldg((const uint2*)(g_kvh + (size_t)src * 256 + 4 * lane));
        uint2 vr = __ldg((const uint2*)(g_kvh + (size_t)src * 256 + 128 + 4 * lane));
        uint2 qr = __ldg((const uint2*)(g_qh  + (size_t)dst * 128 + 4 * lane));
        float2 t2;
        t2 = __half22float2(*(half2*)&kr.x); u64t klo = pk2(t2.x, t2.y);
        t2 = __half22float2(*(half2*)&kr.y); u64t khi = pk2(t2.x, t2.y);
        t2 = __half22float2(*(half2*)&vr.x); u64t vlo = pk2(t2.x, t2.y);
        t2 = __half22float2(*(half2*)&vr.y); u64t vhi = pk2(t2.x, t2.y);
        t2 = __half22float2(*(half2*)&qr.x); u64t qlo = pk2(t2.x, t2.y);
        t2 = __half22float2(*(half2*)&qr.y); u64t qhi = pk2(t2.x, t2.y);

        float2 G2 = *(const float2*)(g_G + (size_t)dst * 64 + h * 16 + 2 * r);

        // alpha
        float e0 = __shfl_sync(FULL, eav, 2 * r);
        float e1 = __shfl_sync(FULL, eav, 2 * r + 1);
        u64t tt = fma2_(qlo, klo, mul2_(qhi, khi));
        float tl, th;
        up2(tl, th, tt);
        float p = tl + th + e0 * G2.x + e1 * G2.y;
        p += __shfl_xor_sync(FULL, p, 1);
        p += __shfl_xor_sync(FULL, p, 2);
        p += __shfl_xor_sync(FULL, p, 4);
        float ex = __expf(p * inv_sqrt_c);
        if (r == 0) atomicAdd(g_denom + (size_t)dst * 4 + h, ex);

        // sbf slice for this lane's head (4 distinct 16B addrs per warp)
        const float4* sp = (const float4*)(sbf + (size_t)e * 64 + h * 16);
        float4 sb0[4];
        #pragma unroll
        for (int i = 0; i < 4; i++) sb0[i] = __ldg(sp + i);

        // sbf filter GEMV (smem reads are 128B/access -> cheap)
        u64t sfl = 0, sfh = 0;
        #pragma unroll
        for (int i = 0; i < 16; i++) {
            float a = c4(sb0[i >> 2], i & 3);
            ulonglong2 w = *(const ulonglong2*)(sw_sf + i * 32 + 4 * r);
            u64t pa = pk2(a, a);
            sfl = fma2_(pa, w.x, sfl);
            sfh = fma2_(pa, w.y, sfh);
        }

        // message = (value + edge_val) * ex * sf
        u64t pex = pk2(ex, ex);
        u64t ml = mul2_(mul2_(add2_(vlo, evl), sfl), pex);
        u64t mh = mul2_(mul2_(add2_(vhi, evh), sfh), pex);
        float4 m;
        up2(m.x, m.y, ml); up2(m.z, m.w, mh);
        atomicAdd((float4*)(g_aggr + (size_t)dst * 128 + 4 * lane), m);
    }
}

// ---------------- K3: normalize + add skip ----------------
__global__ __launch_bounds__(256)
void finalize_kernel(float* __restrict__ out)
{
    int t = blockIdx.x * blockDim.x + threadIdx.x;
    if (t >= NN * 32) return;
    int n = t >> 5;
    int g = t & 31;
    float d = g_denom[n * 4 + (g >> 3)];
    float inv = (d > 0.f) ? 1.0f / d : 0.f;
    float4 a = *(const float4*)(g_aggr + n * 128 + 4 * g);
    float4 o = *(const float4*)(out + n * 128 + 4 * g);
    o.x = fmaf(a.x, inv, o.x);
    o.y = fmaf(a.y, inv, o.y);
    o.z = fmaf(a.z, inv, o.z);
    o.w = fmaf(a.w, inv, o.w);
    *(float4*)(out + n * 128 + 4 * g) = o;
}

// ---------------- host ----------------
extern "C" void kernel_launch(void* const* d_in, const int* in_sizes, int n_in,
                              void* d_out, int out_size)
{
    const float* x         = (const float*)d_in[0];
    const float* edge_attr = (const float*)d_in[1];
    const float* rbf       = (const float*)d_in[2];
    const float* sbf       = (const float*)d_in[3];
    const float* w_rbf0    = (const float*)d_in[4];
    const float* w_rbf1    = (const float*)d_in[5];
    const float* w_sbf0    = (const float*)d_in[6];
    const float* w_sbf1    = (const float*)d_in[7];
    const float* w_ek      = (const float*)d_in[8];
    const float* w_ev      = (const float*)d_in[9];
    const float* w_k       = (const float*)d_in[10];
    const float* b_k       = (const float*)d_in[11];
    const float* w_q       = (const float*)d_in[12];
    const float* b_q       = (const float*)d_in[13];
    const float* w_v       = (const float*)d_in[14];
    const float* b_v       = (const float*)d_in[15];
    const float* w_skip    = (const float*)d_in[16];
    const float* b_skip    = (const float*)d_in[17];
    const int*   ei        = (const int*)d_in[18];
    float* out = (float*)d_out;

    void *p_aggr, *p_denom;
    cudaGetSymbolAddress(&p_aggr, g_aggr);
    cudaGetSymbolAddress(&p_denom, g_denom);
    cudaMemsetAsync(p_aggr, 0, (size_t)NN * 128 * sizeof(float));   // launch 1
    cudaMemsetAsync(p_denom, 0, (size_t)NN * 4 * sizeof(float));    // launch 2

    combine_weights_kernel<<<6, 256>>>(w_rbf0, w_rbf1, w_sbf0, w_sbf1);  // launch 3

    int smem = 20288 * (int)sizeof(float);  // 81152 B -> 2 CTA/SM
    cudaFuncSetAttribute(node_kernel, cudaFuncAttributeMaxDynamicSharedMemorySize, smem);
    node_kernel<<<296, 256, smem>>>(x, rbf, w_ek, w_k, b_k, w_q, b_q,
                                    w_v, b_v, w_skip, b_skip, out);       // launch 4

    profile_align_kernel<<<1, 32>>>();                                    // launch 5

    edge_kernel<<<296, 256>>>(edge_attr, sbf, w_ev, ei);                  // launch 6 <- ncu -s 5

    finalize_kernel<<<(NN * 32 + 255) / 256, 256>>>(out);                 // launch 7
}

// round 15
// speedup vs baseline: 1.2943x; 1.2943x over previous
#include <cuda_runtime.h>
#include <cuda_fp16.h>

#define NN 100000
#define EE 800000
#define FULL 0xffffffffu

typedef unsigned long long u64t;

// ---- f32x2 packed-math helpers (Blackwell FFMA2 path, PTX-only) ----
__device__ __forceinline__ u64t pk2(float lo, float hi) {
    u64t r; asm("mov.b64 %0, {%1, %2};" : "=l"(r) : "f"(lo), "f"(hi)); return r;
}
__device__ __forceinline__ void up2(float& lo, float& hi, u64t v) {
    asm("mov.b64 {%0, %1}, %2;" : "=f"(lo), "=f"(hi) : "l"(v));
}
__device__ __forceinline__ u64t fma2_(u64t a, u64t b, u64t c) {
    u64t d; asm("fma.rn.f32x2 %0, %1, %2, %3;" : "=l"(d) : "l"(a), "l"(b), "l"(c)); return d;
}
__device__ __forceinline__ u64t mul2_(u64t a, u64t b) {
    u64t d; asm("mul.rn.f32x2 %0, %1, %2;" : "=l"(d) : "l"(a), "l"(b)); return d;
}
__device__ __forceinline__ u64t add2_(u64t a, u64t b) {
    u64t d; asm("add.rn.f32x2 %0, %1, %2;" : "=l"(d) : "l"(a), "l"(b)); return d;
}
__device__ __forceinline__ float c4(const float4 v, int k) {
    return k == 0 ? v.x : k == 1 ? v.y : k == 2 ? v.z : v.w;
}

// ---------------- device scratch (no allocs allowed) ----------------
__device__ __half g_kvh[NN * 256];   // [n][0:128)=key, [n][128:256)=value, fp16
__device__ __half g_qh[NN * 128];    // query, fp16
__device__ float  g_aggr[NN * 128];
__device__ float  g_G[NN * 64];
__device__ float  g_denom[NN * 4];
__device__ float  g_wrbf[42 * 32];
__device__ float  g_wsbf[16 * 32];

// ---------------- K0: fold weight pairs ----------------
__global__ void combine_weights_kernel(const float* __restrict__ w_rbf0,
                                       const float* __restrict__ w_rbf1,
                                       const float* __restrict__ w_sbf0,
                                       const float* __restrict__ w_sbf1)
{
    int t = blockIdx.x * blockDim.x + threadIdx.x;
    if (t < 42 * 32) {
        int i = t >> 5, o = t & 31;
        float s = 0.f;
        #pragma unroll
        for (int k = 0; k < 32; k++) s = fmaf(w_rbf0[i * 32 + k], w_rbf1[k * 32 + o], s);
        g_wrbf[t] = s;
    }
    if (t < 16 * 32) {
        int i = t >> 5, o = t & 31;
        float s = 0.f;
        #pragma unroll
        for (int k = 0; k < 32; k++) s = fmaf(w_sbf0[i * 32 + k], w_sbf1[k * 32 + o], s);
        g_wsbf[t] = s;
    }
}

// ---------------- dummy: aligns ncu -s 5 onto edge_kernel ----------------
__global__ void profile_align_kernel() {}

// ---------------- K1: per-node K/Q/V/skip + G, 4 nodes per warp iter ----------------
__global__ __launch_bounds__(256, 2)
void node_kernel(const float* __restrict__ x, const float* __restrict__ rbf,
                 const float* __restrict__ w_ek,
                 const float* __restrict__ w_k, const float* __restrict__ b_k,
                 const float* __restrict__ w_q, const float* __restrict__ b_q,
                 const float* __restrict__ w_v, const float* __restrict__ b_v,
                 const float* __restrict__ w_skip, const float* __restrict__ b_skip,
                 float* __restrict__ out)
{
    extern __shared__ float sm[];
    float* sw_k    = sm;
    float* sw_q    = sm + 4096;
    float* sw_v    = sm + 8192;
    float* sw_s    = sm + 12288;
    float* sw_ek   = sm + 16384;
    float* sw_rbfc = sm + 18432;
    float* sb      = sm + 19776;

    for (int i = threadIdx.x; i < 4096; i += blockDim.x) {
        sw_k[i] = w_k[i]; sw_q[i] = w_q[i]; sw_v[i] = w_v[i]; sw_s[i] = w_skip[i];
    }
    for (int i = threadIdx.x; i < 2048; i += blockDim.x) sw_ek[i] = w_ek[i];
    for (int i = threadIdx.x; i < 1344; i += blockDim.x) sw_rbfc[i] = g_wrbf[i];
    for (int i = threadIdx.x; i < 128; i += blockDim.x) {
        sb[i] = b_k[i]; sb[128 + i] = b_q[i]; sb[256 + i] = b_v[i]; sb[384 + i] = b_skip[i];
    }
    __syncthreads();

    int lane = threadIdx.x & 31;
    int r = lane & 7;
    int gw = (blockIdx.x * blockDim.x + threadIdx.x) >> 5;
    int nw = (gridDim.x * blockDim.x) >> 5;

    for (int n0 = gw * 4; n0 < NN; n0 += nw * 4) {
        float f[4] = {0.f, 0.f, 0.f, 0.f};
        const float* rn = rbf + (size_t)n0 * 42;
        #pragma unroll 6
        for (int i = 0; i < 42; i++) {
            float w = sw_rbfc[i * 32 + lane];
            f[0] = fmaf(__ldg(rn + i),       w, f[0]);
            f[1] = fmaf(__ldg(rn + 42 + i),  w, f[1]);
            f[2] = fmaf(__ldg(rn + 84 + i),  w, f[2]);
            f[3] = fmaf(__ldg(rn + 126 + i), w, f[3]);
        }
        float xv[4], xs[4];
        #pragma unroll
        for (int j = 0; j < 4; j++) {
            xv[j] = __ldg(x + (size_t)(n0 + j) * 32 + lane);
            xs[j] = f[j] * xv[j];
        }

        ulonglong2 bK = *(const ulonglong2*)(sb + 4 * lane);
        ulonglong2 bQ = *(const ulonglong2*)(sb + 128 + 4 * lane);
        ulonglong2 bV = *(const ulonglong2*)(sb + 256 + 4 * lane);
        ulonglong2 bS = *(const ulonglong2*)(sb + 384 + 4 * lane);
        u64t aK[4][2], aQ[4][2], aV[4][2], aS[4][2];
        #pragma unroll
        for (int j = 0; j < 4; j++) {
            aK[j][0] = bK.x; aK[j][1] = bK.y;
            aQ[j][0] = bQ.x; aQ[j][1] = bQ.y;
            aV[j][0] = bV.x; aV[j][1] = bV.y;
            aS[j][0] = bS.x; aS[j][1] = bS.y;
        }

        #pragma unroll 8
        for (int c = 0; c < 32; c++) {
            ulonglong2 wk = *(const ulonglong2*)(sw_k + c * 128 + 4 * lane);
            ulonglong2 wq = *(const ulonglong2*)(sw_q + c * 128 + 4 * lane);
            ulonglong2 wv = *(const ulonglong2*)(sw_v + c * 128 + 4 * lane);
            ulonglong2 ws = *(const ulonglong2*)(sw_s + c * 128 + 4 * lane);
            #pragma unroll
            for (int j = 0; j < 4; j++) {
                float ms = __shfl_sync(FULL, xs[j], c);
                float mx = __shfl_sync(FULL, xv[j], c);
                u64t pms = pk2(ms, ms);
                u64t pmx = pk2(mx, mx);
                aK[j][0] = fma2_(pms, wk.x, aK[j][0]); aK[j][1] = fma2_(pms, wk.y, aK[j][1]);
                aQ[j][0] = fma2_(pmx, wq.x, aQ[j][0]); aQ[j][1] = fma2_(pmx, wq.y, aQ[j][1]);
                aV[j][0] = fma2_(pms, wv.x, aV[j][0]); aV[j][1] = fma2_(pms, wv.y, aV[j][1]);
                aS[j][0] = fma2_(pmx, ws.x, aS[j][0]); aS[j][1] = fma2_(pmx, ws.y, aS[j][1]);
            }
        }

        #pragma unroll
        for (int j = 0; j < 4; j++) {
            float4 K, V, Q, S;
            up2(K.x, K.y, aK[j][0]); up2(K.z, K.w, aK[j][1]);
            up2(V.x, V.y, aV[j][0]); up2(V.z, V.w, aV[j][1]);
            up2(Q.x, Q.y, aQ[j][0]); up2(Q.z, Q.w, aQ[j][1]);
            up2(S.x, S.y, aS[j][0]); up2(S.z, S.w, aS[j][1]);
            uint2 st;
            *(half2*)&st.x = __floats2half2_rn(K.x, K.y);
            *(half2*)&st.y = __floats2half2_rn(K.z, K.w);
            *(uint2*)(g_kvh + (size_t)(n0 + j) * 256 + 4 * lane) = st;
            *(half2*)&st.x = __floats2half2_rn(V.x, V.y);
            *(half2*)&st.y = __floats2half2_rn(V.z, V.w);
            *(uint2*)(g_kvh + (size_t)(n0 + j) * 256 + 128 + 4 * lane) = st;
            *(half2*)&st.x = __floats2half2_rn(Q.x, Q.y);
            *(half2*)&st.y = __floats2half2_rn(Q.z, Q.w);
            *(uint2*)(g_qh + (size_t)(n0 + j) * 128 + 4 * lane) = st;
            ulonglong2 o;
            o.x = aS[j][0]; o.y = aS[j][1];
            *(ulonglong2*)(out + (size_t)(n0 + j) * 128 + 4 * lane) = o;
        }

        // G[n][h][i] = sum_{c in head h} w_ek[i][h*32+c] * query[h*32+c]  (f32 q)
        float4 q[4];
        #pragma unroll
        for (int j = 0; j < 4; j++) {
            up2(q[j].x, q[j].y, aQ[j][0]);
            up2(q[j].z, q[j].w, aQ[j][1]);
        }
        float G0[4] = {0.f,0.f,0.f,0.f}, G1[4] = {0.f,0.f,0.f,0.f};
        #pragma unroll
        for (int i = 0; i < 16; i++) {
            float4 we = *(const float4*)(sw_ek + i * 128 + 4 * lane);
            #pragma unroll
            for (int j = 0; j < 4; j++) {
                float p = we.x * q[j].x + we.y * q[j].y + we.z * q[j].z + we.w * q[j].w;
                p += __shfl_xor_sync(FULL, p, 1);
                p += __shfl_xor_sync(FULL, p, 2);
                p += __shfl_xor_sync(FULL, p, 4);
                if ((i >> 1) == r) { if (i & 1) G1[j] = p; else G0[j] = p; }
            }
        }
        #pragma unroll
        for (int j = 0; j < 4; j++)
            *(float2*)(g_G + (size_t)(n0 + j) * 64 + (lane >> 3) * 16 + 2 * r)
                = make_float2(G0[j], G1[j]);
    }
}

// ---------------- K2: edge pass, 2 edges/iter (MLP), smem w_ev, fp16 gathers ----------------
__global__ __launch_bounds__(256, 2)
void edge_kernel(const float* __restrict__ edge_attr, const float* __restrict__ sbf,
                 const float* __restrict__ w_ev, const int* __restrict__ ei)
{
    __shared__ __align__(16) float sw_ev[2048];
    __shared__ __align__(16) float sw_sf[512];
    for (int i = threadIdx.x; i < 2048; i += blockDim.x) sw_ev[i] = w_ev[i];
    for (int i = threadIdx.x; i < 512; i += blockDim.x) sw_sf[i] = g_wsbf[i];
    __syncthreads();

    int lane = threadIdx.x & 31;
    int r = lane & 7;
    int h = lane >> 3;
    int gw = (blockIdx.x * blockDim.x + threadIdx.x) >> 5;
    int nw = (gridDim.x * blockDim.x) >> 5;
    const float inv_sqrt_c = 0.17677669529663687f;

    for (int e = gw * 2; e < EE; e += nw * 2) {
        int s0 = __ldg(ei + e);
        int s1 = __ldg(ei + e + 1);
        int d0 = __ldg(ei + EE + e);
        int d1 = __ldg(ei + EE + e + 1);

        const float4* eap = (const float4*)(edge_attr + (size_t)e * 16);
        float4 ea0[4], ea1[4];
        #pragma unroll
        for (int i = 0; i < 4; i++) { ea0[i] = __ldg(eap + i); ea1[i] = __ldg(eap + 4 + i); }
        float eav0 = __ldg(edge_attr + (size_t)e * 16 + (lane & 15));
        float eav1 = __ldg(edge_attr + (size_t)(e + 1) * 16 + (lane & 15));

        // fp16 gathers early (independent -> MLP under the GEMV compute)
        uint2 kr0 = __ldg((const uint2*)(g_kvh + (size_t)s0 * 256 + 4 * lane));
        uint2 vr0 = __ldg((const uint2*)(g_kvh + (size_t)s0 * 256 + 128 + 4 * lane));
        uint2 kr1 = __ldg((const uint2*)(g_kvh + (size_t)s1 * 256 + 4 * lane));
        uint2 vr1 = __ldg((const uint2*)(g_kvh + (size_t)s1 * 256 + 128 + 4 * lane));
        uint2 qr0 = __ldg((const uint2*)(g_qh  + (size_t)d0 * 128 + 4 * lane));
        uint2 qr1 = __ldg((const uint2*)(g_qh  + (size_t)d1 * 128 + 4 * lane));
        float2 Ga = *(const float2*)(g_G + (size_t)d0 * 64 + h * 16 + 2 * r);
        float2 Gb = *(const float2*)(g_G + (size_t)d1 * 64 + h * 16 + 2 * r);

        // edge_val GEMV for both edges, shared weight LDS, f32x2
        u64t ev0l = 0, ev0h = 0, ev1l = 0, ev1h = 0;
        #pragma unroll
        for (int i = 0; i < 16; i++) {
            float a0 = c4(ea0[i >> 2], i & 3);
            float a1 = c4(ea1[i >> 2], i & 3);
            ulonglong2 w = *(const ulonglong2*)(sw_ev + i * 128 + 4 * lane);
            u64t pa0 = pk2(a0, a0);
            u64t pa1 = pk2(a1, a1);
            ev0l = fma2_(pa0, w.x, ev0l); ev0h = fma2_(pa0, w.y, ev0h);
            ev1l = fma2_(pa1, w.x, ev1l); ev1h = fma2_(pa1, w.y, ev1h);
        }

        // unpack fp16 gathers to packed f32x2
        float2 t2;
        t2 = __half22float2(*(half2*)&kr0.x); u64t k0l = pk2(t2.x, t2.y);
        t2 = __half22float2(*(half2*)&kr0.y); u64t k0h = pk2(t2.x, t2.y);
        t2 = __half22float2(*(half2*)&kr1.x); u64t k1l = pk2(t2.x, t2.y);
        t2 = __half22float2(*(half2*)&kr1.y); u64t k1h = pk2(t2.x, t2.y);
        t2 = __half22float2(*(half2*)&vr0.x); u64t v0l = pk2(t2.x, t2.y);
        t2 = __half22float2(*(half2*)&vr0.y); u64t v0h = pk2(t2.x, t2.y);
        t2 = __half22float2(*(half2*)&vr1.x); u64t v1l = pk2(t2.x, t2.y);
        t2 = __half22float2(*(half2*)&vr1.y); u64t v1h = pk2(t2.x, t2.y);
        t2 = __half22float2(*(half2*)&qr0.x); u64t q0l = pk2(t2.x, t2.y);
        t2 = __half22float2(*(half2*)&qr0.y); u64t q0h = pk2(t2.x, t2.y);
        t2 = __half22float2(*(half2*)&qr1.x); u64t q1l = pk2(t2.x, t2.y);
        t2 = __half22float2(*(half2*)&qr1.y); u64t q1h = pk2(t2.x, t2.y);

        // alpha
        float e00 = __shfl_sync(FULL, eav0, 2 * r);
        float e01 = __shfl_sync(FULL, eav0, 2 * r + 1);
        float e10 = __shfl_sync(FULL, eav1, 2 * r);
        float e11 = __shfl_sync(FULL, eav1, 2 * r + 1);
        u64t t0 = fma2_(q0l, k0l, mul2_(q0h, k0h));
        u64t t1 = fma2_(q1l, k1l, mul2_(q1h, k1h));
        float tl, th;
        up2(tl, th, t0);
        float p0 = tl + th + e00 * Ga.x + e01 * Ga.y;
        up2(tl, th, t1);
        float p1 = tl + th + e10 * Gb.x + e11 * Gb.y;
        p0 += __shfl_xor_sync(FULL, p0, 1);
        p0 += __shfl_xor_sync(FULL, p0, 2);
        p0 += __shfl_xor_sync(FULL, p0, 4);
        p1 += __shfl_xor_sync(FULL, p1, 1);
        p1 += __shfl_xor_sync(FULL, p1, 2);
        p1 += __shfl_xor_sync(FULL, p1, 4);
        float ex0 = __expf(p0 * inv_sqrt_c);
        float ex1 = __expf(p1 * inv_sqrt_c);
        if (r == 0) {
            atomicAdd(g_denom + (size_t)d0 * 4 + h, ex0);
            atomicAdd(g_denom + (size_t)d1 * 4 + h, ex1);
        }

        // sbf slices for this lane's head
        const float4* sp0 = (const float4*)(sbf + (size_t)e * 64 + h * 16);
        float4 sb0[4], sb1[4];
        #pragma unroll
        for (int i = 0; i < 4; i++) { sb0[i] = __ldg(sp0 + i); sb1[i] = __ldg(sp0 + 16 + i); }

        // sbf filter GEMV, f32x2
        u64t sf0l = 0, sf0h = 0, sf1l = 0, sf1h = 0;
        #pragma unroll
        for (int i = 0; i < 16; i++) {
            float a0 = c4(sb0[i >> 2], i & 3);
            float a1 = c4(sb1[i >> 2], i & 3);
            ulonglong2 w = *(const ulonglong2*)(sw_sf + i * 32 + 4 * r);
            u64t pa0 = pk2(a0, a0);
            u64t pa1 = pk2(a1, a1);
            sf0l = fma2_(pa0, w.x, sf0l); sf0h = fma2_(pa0, w.y, sf0h);
            sf1l = fma2_(pa1, w.x, sf1l); sf1h = fma2_(pa1, w.y, sf1h);
        }

        // message = (value + edge_val) * ex * sf
        u64t pex0 = pk2(ex0, ex0);
        u64t pex1 = pk2(ex1, ex1);
        u64t m0l = mul2_(mul2_(add2_(v0l, ev0l), sf0l), pex0);
        u64t m0h = mul2_(mul2_(add2_(v0h, ev0h), sf0h), pex0);
        u64t m1l = mul2_(mul2_(add2_(v1l, ev1l), sf1l), pex1);
        u64t m1h = mul2_(mul2_(add2_(v1h, ev1h), sf1h), pex1);
        float4 m0, m1;
        up2(m0.x, m0.y, m0l); up2(m0.z, m0.w, m0h);
        up2(m1.x, m1.y, m1l); up2(m1.z, m1.w, m1h);
        atomicAdd((float4*)(g_aggr + (size_t)d0 * 128 + 4 * lane), m0);
        atomicAdd((float4*)(g_aggr + (size_t)d1 * 128 + 4 * lane), m1);
    }
}

// ---------------- K3: normalize + add skip ----------------
__global__ __launch_bounds__(256)
void finalize_kernel(float* __restrict__ out)
{
    int t = blockIdx.x * blockDim.x + threadIdx.x;
    if (t >= NN * 32) return;
    int n = t >> 5;
    int g = t & 31;
    float d = g_denom[n * 4 + (g >> 3)];
    float inv = (d > 0.f) ? 1.0f / d : 0.f;
    float4 a = *(const float4*)(g_aggr + n * 128 + 4 * g);
    float4 o = *(const float4*)(out + n * 128 + 4 * g);
    o.x = fmaf(a.x, inv, o.x);
    o.y = fmaf(a.y, inv, o.y);
    o.z = fmaf(a.z, inv, o.z);
    o.w = fmaf(a.w, inv, o.w);
    *(float4*)(out + n * 128 + 4 * g) = o;
}

// ---------------- host ----------------
extern "C" void kernel_launch(void* const* d_in, const int* in_sizes, int n_in,
                              void* d_out, int out_size)
{
    const float* x         = (const float*)d_in[0];
    const float* edge_attr = (const float*)d_in[1];
    const float* rbf       = (const float*)d_in[2];
    const float* sbf       = (const float*)d_in[3];
    const float* w_rbf0    = (const float*)d_in[4];
    const float* w_rbf1    = (const float*)d_in[5];
    const float* w_sbf0    = (const float*)d_in[6];
    const float* w_sbf1    = (const float*)d_in[7];
    const float* w_ek      = (const float*)d_in[8];
    const float* w_ev      = (const float*)d_in[9];
    const float* w_k       = (const float*)d_in[10];
    const float* b_k       = (const float*)d_in[11];
    const float* w_q       = (const float*)d_in[12];
    const float* b_q       = (const float*)d_in[13];
    const float* w_v       = (const float*)d_in[14];
    const float* b_v       = (const float*)d_in[15];
    const float* w_skip    = (const float*)d_in[16];
    const float* b_skip    = (const float*)d_in[17];
    const int*   ei        = (const int*)d_in[18];
    float* out = (float*)d_out;

    void *p_aggr, *p_denom;
    cudaGetSymbolAddress(&p_aggr, g_aggr);
    cudaGetSymbolAddress(&p_denom, g_denom);
    cudaMemsetAsync(p_aggr, 0, (size_t)NN * 128 * sizeof(float));   // launch 1
    cudaMemsetAsync(p_denom, 0, (size_t)NN * 4 * sizeof(float));    // launch 2

    combine_weights_kernel<<<6, 256>>>(w_rbf0, w_rbf1, w_sbf0, w_sbf1);  // launch 3

    int smem = 20288 * (int)sizeof(float);  // 81152 B -> 2 CTA/SM
    cudaFuncSetAttribute(node_kernel, cudaFuncAttributeMaxDynamicSharedMemorySize, smem);
    node_kernel<<<296, 256, smem>>>(x, rbf, w_ek, w_k, b_k, w_q, b_q,
                                    w_v, b_v, w_skip, b_skip, out);       // launch 4

    profile_align_kernel<<<1, 32>>>();                                    // launch 5

    edge_kernel<<<296, 256>>>(edge_attr, sbf, w_ev, ei);                  // launch 6 <- ncu -s 5

    finalize_kernel<<<(NN * 32 + 255) / 256, 256>>>(out);                 // launch 7
}